// round 3
// baseline (speedup 1.0000x reference)
#include <cuda_runtime.h>
#include <math.h>

#define Bn 1024
#define Sn 50
#define En 300
#define Hn 200
#define G3 600

typedef unsigned long long ull;

// ---------------- scratch (device globals; no allocation allowed) ----------
__device__ float g_gx_f[Bn * Sn * G3];
__device__ float g_gx_b[Bn * Sn * G3];
__device__ float g_hf[Bn * Sn * Hn];
__device__ float g_hb[Bn * Sn * Hn];
__device__ float g_sent[Bn * Sn * Hn];
__device__ float g_novp[Bn * Sn * Hn];
__device__ float g_hcur[2][2][Bn * Hn];   // [parity][dir][b*H]
__device__ float g_base[Bn * Sn];
__device__ float g_avg[Bn * Hn];
__device__ float g_doc[Bn * Hn];

// ---------------- helpers ---------------------------------------------------
__device__ __forceinline__ void ffma2(ull& d, ull a, ull b) {
    asm("fma.rn.f32x2 %0, %1, %2, %3;" : "=l"(d) : "l"(a), "l"(b), "l"(d));
}
__device__ __forceinline__ float f2sum(ull v) {
    float lo, hi;
    asm("mov.b64 {%0,%1}, %2;" : "=f"(lo), "=f"(hi) : "l"(v));
    return lo + hi;
}
__device__ __forceinline__ float sigf(float x) { return 1.f / (1.f + expf(-x)); }

// ---------------- zero ------------------------------------------------------
__global__ void zero_kernel(float* p, int n) {
    int i = blockIdx.x * blockDim.x + threadIdx.x;
    if (i < n) p[i] = 0.f;
}

// ---------------- position logits + bias -> g_base --------------------------
__global__ void pos_kernel(const int* __restrict__ ap, const int* __restrict__ rp,
                           const float* __restrict__ at, const float* __restrict__ rt,
                           const float* __restrict__ aw, const float* __restrict__ ab,
                           const float* __restrict__ rw, const float* __restrict__ rb,
                           const float* __restrict__ bias) {
    int idx = blockIdx.x * blockDim.x + threadIdx.x;
    if (idx >= Bn * Sn) return;
    int a = min(max(ap[idx], 0), 50);
    int r = min(max(rp[idx], 0), 4);
    float al = ab[0], rl = rb[0];
#pragma unroll 10
    for (int p = 0; p < 50; p++) {
        al += at[a * 50 + p] * aw[p];
        rl += rt[r * 50 + p] * rw[p];
    }
    g_base[idx] = al + rl + bias[0];
}

// ---------------- generic C = act(A @ W^T + bias) ---------------------------
// A row m: cols [0,KA) from A1 (leading dim lda1), cols [KA,K) from A2.
// W is [N, K] row major. C is [M, N] row major. Tile 64x64x16, FFMA2 micro 4x4.
__global__ __launch_bounds__(256) void gemm_atb(
    const float* __restrict__ A1, int lda1, int KA,
    const float* __restrict__ A2, int lda2,
    const float* __restrict__ W, const float* __restrict__ bias,
    float* __restrict__ C, int N, int K, int act)
{
    __shared__ float As[64][18];
    __shared__ float Ws[64][18];
    int tid = threadIdx.x;
    int tx = tid & 15, ty = tid >> 4;
    int m0 = blockIdx.x * 64, n0 = blockIdx.y * 64;

    ull acc[4][4];
#pragma unroll
    for (int i = 0; i < 4; i++)
#pragma unroll
        for (int j = 0; j < 4; j++) acc[i][j] = 0ULL;

    int r = tid >> 2;
    int kq = (tid & 3) * 4;

    for (int k0 = 0; k0 < K; k0 += 16) {
#pragma unroll
        for (int q = 0; q < 4; q++) {
            int k = k0 + kq + q;
            float v = 0.f;
            if (k < K) {
                size_t m = (size_t)(m0 + r);
                v = (k < KA) ? A1[m * (size_t)lda1 + k]
                             : A2[m * (size_t)lda2 + (k - KA)];
            }
            As[r][kq + q] = v;
        }
#pragma unroll
        for (int q = 0; q < 4; q++) {
            int k = k0 + kq + q;
            int n = n0 + r;
            float v = 0.f;
            if (k < K && n < N) v = W[(size_t)n * K + k];
            Ws[r][kq + q] = v;
        }
        __syncthreads();
#pragma unroll
        for (int kk = 0; kk < 16; kk += 2) {
            ull a2[4], w2[4];
#pragma unroll
            for (int i = 0; i < 4; i++) a2[i] = *(const ull*)&As[ty + 16 * i][kk];
#pragma unroll
            for (int j = 0; j < 4; j++) w2[j] = *(const ull*)&Ws[tx + 16 * j][kk];
#pragma unroll
            for (int i = 0; i < 4; i++)
#pragma unroll
                for (int j = 0; j < 4; j++) ffma2(acc[i][j], a2[i], w2[j]);
        }
        __syncthreads();
    }

#pragma unroll
    for (int i = 0; i < 4; i++) {
        int m = m0 + ty + 16 * i;
#pragma unroll
        for (int j = 0; j < 4; j++) {
            int n = n0 + tx + 16 * j;
            if (n < N) {
                float v = f2sum(acc[i][j]) + bias[n];
                if (act) v = fmaxf(v, 0.f);
                C[(size_t)m * N + n] = v;
            }
        }
    }
}

// ---------------- GRU step (both directions, gates fused) -------------------
// block: 64 batches x 16 h-cols (x3 gates). grid (16, 13, 2). 128 threads.
__global__ __launch_bounds__(128) void gru_step(
    const float* __restrict__ Whh_f, const float* __restrict__ bhh_f,
    const float* __restrict__ Whh_b, const float* __restrict__ bhh_b,
    int t)
{
    int dir = blockIdx.z;
    const float* Whh = dir ? Whh_b : Whh_f;
    const float* bhh = dir ? bhh_b : bhh_f;
    const float* gx = dir ? g_gx_b : g_gx_f;
    float* hout = dir ? g_hb : g_hf;
    int s = dir ? (Sn - 1 - t) : t;
    int p = t & 1;
    const float* hprev = g_hcur[p][dir];
    float* hnext = g_hcur[p ^ 1][dir];

    __shared__ float hs[64][18];
    __shared__ float ws[48][18];

    int tid = threadIdx.x;
    int tx = tid & 7, ty = tid >> 3;
    int b0 = blockIdx.x * 64, j0 = blockIdx.y * 16;

    ull acc[4][2][3];
#pragma unroll
    for (int i = 0; i < 4; i++)
#pragma unroll
        for (int jj = 0; jj < 2; jj++)
#pragma unroll
            for (int g = 0; g < 3; g++) acc[i][jj][g] = 0ULL;

    for (int k0 = 0; k0 < Hn; k0 += 16) {
#pragma unroll
        for (int q = 0; q < 8; q++) {
            int idx = tid + q * 128;
            int bb = idx >> 4, kk = idx & 15;
            int k = k0 + kk;
            hs[bb][kk] = (k < Hn) ? hprev[(b0 + bb) * Hn + k] : 0.f;
        }
#pragma unroll
        for (int q = 0; q < 6; q++) {
            int idx = tid + q * 128;
            int row = idx >> 4, kk = idx & 15;
            int g = row >> 4, jj = row & 15;
            int j = j0 + jj, k = k0 + kk;
            float v = 0.f;
            if (j < Hn && k < Hn) v = Whh[(size_t)(g * Hn + j) * Hn + k];
            ws[row][kk] = v;
        }
        __syncthreads();
#pragma unroll
        for (int kk = 0; kk < 16; kk += 2) {
            ull a2[4];
#pragma unroll
            for (int i = 0; i < 4; i++) a2[i] = *(const ull*)&hs[ty + 16 * i][kk];
#pragma unroll
            for (int g = 0; g < 3; g++) {
#pragma unroll
                for (int jj = 0; jj < 2; jj++) {
                    ull w2 = *(const ull*)&ws[g * 16 + tx + 8 * jj][kk];
#pragma unroll
                    for (int i = 0; i < 4; i++) ffma2(acc[i][jj][g], a2[i], w2);
                }
            }
        }
        __syncthreads();
    }

#pragma unroll
    for (int i = 0; i < 4; i++) {
#pragma unroll
        for (int jj = 0; jj < 2; jj++) {
            int b = b0 + ty + 16 * i;
            int j = j0 + tx + 8 * jj;
            if (j < Hn) {
                float ghr = f2sum(acc[i][jj][0]) + bhh[j];
                float ghz = f2sum(acc[i][jj][1]) + bhh[Hn + j];
                float ghn = f2sum(acc[i][jj][2]) + bhh[2 * Hn + j];
                size_t gxi = ((size_t)b * Sn + s) * G3 + j;
                float rg = sigf(gx[gxi] + ghr);
                float zg = sigf(gx[gxi + Hn] + ghz);
                float ng = tanhf(gx[gxi + 2 * Hn] + rg * ghn);
                float hp = hprev[b * Hn + j];
                float hv = (1.f - zg) * ng + zg * hp;
                hnext[b * Hn + j] = hv;
                hout[((size_t)b * Sn + s) * Hn + j] = hv;
            }
        }
    }
}

// ---------------- avg over S ------------------------------------------------
__global__ void avg_kernel(const int* __restrict__ length) {
    int idx = blockIdx.x * blockDim.x + threadIdx.x;
    if (idx >= Bn * Hn) return;
    int b = idx / Hn, h = idx % Hn;
    float sm = 0.f;
#pragma unroll 10
    for (int t = 0; t < Sn; t++) sm += g_sent[((size_t)b * Sn + t) * Hn + h];
    g_avg[idx] = sm / (float)length[b];
}

// ---------------- doc = tanh(avg@W1^T+b1)@W2^T+b2 ---------------------------
__global__ __launch_bounds__(256) void doc_kernel(
    const float* __restrict__ W1, const float* __restrict__ b1,
    const float* __restrict__ W2, const float* __restrict__ b2)
{
    __shared__ float sv[Hn];
    __shared__ float st[Hn];
    int b = blockIdx.x, tid = threadIdx.x;
    if (tid < Hn) sv[tid] = g_avg[b * Hn + tid];
    __syncthreads();
    if (tid < Hn) {
        float a = b1[tid];
        for (int k = 0; k < Hn; k++) a += sv[k] * W1[(size_t)tid * Hn + k];
        st[tid] = tanhf(a);
    }
    __syncthreads();
    if (tid < Hn) {
        float a = b2[tid];
        for (int k = 0; k < Hn; k++) a += st[k] * W2[(size_t)tid * Hn + k];
        g_doc[b * Hn + tid] = a;
    }
}

// ---------------- base += content + salience --------------------------------
__global__ __launch_bounds__(256) void basedot_kernel(
    const float* __restrict__ wcont, const float* __restrict__ bcont)
{
    int row = blockIdx.x * 8 + (threadIdx.x >> 5);
    int lane = threadIdx.x & 31;
    int b = row / Sn;
    float a1 = 0.f, a2 = 0.f;
    for (int h = lane; h < Hn; h += 32) {
        float sv = g_sent[(size_t)row * Hn + h];
        a1 += sv * wcont[h];
        a2 += sv * g_doc[b * Hn + h];
    }
#pragma unroll
    for (int o = 16; o; o >>= 1) {
        a1 += __shfl_xor_sync(0xffffffffu, a1, o);
        a2 += __shfl_xor_sync(0xffffffffu, a2, o);
    }
    if (lane == 0) g_base[row] += a1 + bcont[0] + a2;
}

// ---------------- final novelty scan ---------------------------------------
__global__ __launch_bounds__(256) void scan_kernel(float* __restrict__ out) {
    __shared__ float red[8];
    int b = blockIdx.x, tid = threadIdx.x;
    int lane = tid & 31, w = tid >> 5;
    bool act = tid < Hn;
    float summ = 0.f;
    for (int t = 0; t < Sn; t++) {
        float part = 0.f;
        size_t off = ((size_t)b * Sn + t) * Hn + tid;
        if (act) part = g_novp[off] * tanhf(summ);
#pragma unroll
        for (int o = 16; o; o >>= 1) part += __shfl_xor_sync(0xffffffffu, part, o);
        if (lane == 0) red[w] = part;
        __syncthreads();
        float tot = red[0] + red[1] + red[2] + red[3] + red[4] + red[5] + red[6] + red[7];
        float logit = g_base[b * Sn + t] - tot;
        float sg = 1.f / (1.f + expf(-logit));
        if (act) summ += g_sent[off] * sg;
        if (tid == 0) out[b * Sn + t] = logit;
        __syncthreads();
    }
}

// ---------------- launch ----------------------------------------------------
extern "C" void kernel_launch(void* const* d_in, const int* in_sizes, int n_in,
                              void* d_out, int out_size) {
    const float* seq       = (const float*)d_in[0];
    const int*   apos      = (const int*)d_in[1];
    const int*   rpos      = (const int*)d_in[2];
    const int*   length    = (const int*)d_in[3];
    const float* apos_table= (const float*)d_in[4];
    const float* rpos_table= (const float*)d_in[5];
    const float* apos_w    = (const float*)d_in[6];
    const float* apos_b    = (const float*)d_in[7];
    const float* rpos_w    = (const float*)d_in[8];
    const float* rpos_b    = (const float*)d_in[9];
    const float* Wih_f     = (const float*)d_in[10];
    const float* Whh_f     = (const float*)d_in[11];
    const float* bih_f     = (const float*)d_in[12];
    const float* bhh_f     = (const float*)d_in[13];
    const float* Wih_b     = (const float*)d_in[14];
    const float* Whh_b     = (const float*)d_in[15];
    const float* bih_b     = (const float*)d_in[16];
    const float* bhh_b     = (const float*)d_in[17];
    const float* Wsent     = (const float*)d_in[18];
    const float* bsent     = (const float*)d_in[19];
    const float* wcont     = (const float*)d_in[20];
    const float* bcont     = (const float*)d_in[21];
    const float* Wdoc1     = (const float*)d_in[22];
    const float* bdoc1     = (const float*)d_in[23];
    const float* Wdoc2     = (const float*)d_in[24];
    const float* bdoc2     = (const float*)d_in[25];
    const float* Wnov      = (const float*)d_in[26];
    const float* bnov      = (const float*)d_in[27];
    const float* bias      = (const float*)d_in[28];

    float *p_gxf, *p_gxb, *p_hf, *p_hb, *p_sent, *p_novp, *p_hcur;
    cudaGetSymbolAddress((void**)&p_gxf,  g_gx_f);
    cudaGetSymbolAddress((void**)&p_gxb,  g_gx_b);
    cudaGetSymbolAddress((void**)&p_hf,   g_hf);
    cudaGetSymbolAddress((void**)&p_hb,   g_hb);
    cudaGetSymbolAddress((void**)&p_sent, g_sent);
    cudaGetSymbolAddress((void**)&p_novp, g_novp);
    cudaGetSymbolAddress((void**)&p_hcur, g_hcur);

    // zero h state (both parities, both dirs)
    {
        int n = 2 * 2 * Bn * Hn;
        zero_kernel<<<(n + 255) / 256, 256>>>(p_hcur, n);
    }

    // position logits + bias
    pos_kernel<<<(Bn * Sn + 255) / 256, 256>>>(apos, rpos, apos_table, rpos_table,
                                               apos_w, apos_b, rpos_w, rpos_b, bias);

    // gx GEMMs: [51200,300] @ [600,300]^T
    gemm_atb<<<dim3(Bn * Sn / 64, 10), 256>>>(seq, En, En, seq, En,
                                              Wih_f, bih_f, p_gxf, G3, En, 0);
    gemm_atb<<<dim3(Bn * Sn / 64, 10), 256>>>(seq, En, En, seq, En,
                                              Wih_b, bih_b, p_gxb, G3, En, 0);

    // GRU recurrence
    for (int t = 0; t < Sn; t++) {
        gru_step<<<dim3(Bn / 64, (Hn + 15) / 16, 2), 128>>>(Whh_f, bhh_f, Whh_b, bhh_b, t);
    }

    // sent = relu([hf|hb] @ Wsent^T + bsent)
    gemm_atb<<<dim3(Bn * Sn / 64, (Hn + 63) / 64), 256>>>(p_hf, Hn, Hn, p_hb, Hn,
                                                          Wsent, bsent, p_sent, Hn, 2 * Hn, 1);

    // avg over S, doc MLP
    avg_kernel<<<(Bn * Hn + 255) / 256, 256>>>(length);
    doc_kernel<<<Bn, 256>>>(Wdoc1, bdoc1, Wdoc2, bdoc2);

    // nov_pre = sent @ Wnov^T + bnov
    gemm_atb<<<dim3(Bn * Sn / 64, (Hn + 63) / 64), 256>>>(p_sent, Hn, Hn, p_sent, Hn,
                                                          Wnov, bnov, p_novp, Hn, Hn, 0);

    // base += content + salience
    basedot_kernel<<<Bn * Sn / 8, 256>>>(wcont, bcont);

    // final scan -> logits
    scan_kernel<<<Bn, 256>>>((float*)d_out);
}

// round 10
// speedup vs baseline: 1.0350x; 1.0350x over previous
#include <cuda_runtime.h>
#include <math.h>

#define Bn 1024
#define Sn 50
#define En 300
#define Hn 200
#define G3 600

typedef unsigned long long ull;

// ---------------- scratch (device globals; no allocation allowed) ----------
__device__ float g_gx_f[Bn * Sn * G3];
__device__ float g_gx_b[Bn * Sn * G3];
__device__ float g_hf[Bn * Sn * Hn];
__device__ float g_hb[Bn * Sn * Hn];
__device__ float g_sent[Bn * Sn * Hn];
__device__ float g_novp[Bn * Sn * Hn];
__device__ float g_hcur[2][2][Bn * Hn];   // [parity][dir][b*H]
__device__ float g_base[Bn * Sn];
__device__ float g_avg[Bn * Hn];
__device__ float g_doc[Bn * Hn];

// ---------------- helpers ---------------------------------------------------
__device__ __forceinline__ void ffma2(ull& d, ull a, ull b) {
    asm("fma.rn.f32x2 %0, %1, %2, %3;" : "=l"(d) : "l"(a), "l"(b), "l"(d));
}
__device__ __forceinline__ float f2sum(ull v) {
    float lo, hi;
    asm("mov.b64 {%0,%1}, %2;" : "=f"(lo), "=f"(hi) : "l"(v));
    return lo + hi;
}
__device__ __forceinline__ float sigf(float x) { return 1.f / (1.f + expf(-x)); }

// ---------------- zero ------------------------------------------------------
__global__ void zero_kernel(float* p, int n) {
    int i = blockIdx.x * blockDim.x + threadIdx.x;
    if (i < n) p[i] = 0.f;
}

// ---------------- position logits + bias -> g_base --------------------------
__global__ void pos_kernel(const int* __restrict__ ap, const int* __restrict__ rp,
                           const float* __restrict__ at, const float* __restrict__ rt,
                           const float* __restrict__ aw, const float* __restrict__ ab,
                           const float* __restrict__ rw, const float* __restrict__ rb,
                           const float* __restrict__ bias) {
    int idx = blockIdx.x * blockDim.x + threadIdx.x;
    if (idx >= Bn * Sn) return;
    int a = min(max(ap[idx], 0), 50);
    int r = min(max(rp[idx], 0), 4);
    float al = ab[0], rl = rb[0];
#pragma unroll 10
    for (int p = 0; p < 50; p++) {
        al += at[a * 50 + p] * aw[p];
        rl += rt[r * 50 + p] * rw[p];
    }
    g_base[idx] = al + rl + bias[0];
}

// ---------------- generic C = act(A @ W^T + bias) ---------------------------
// 128x128 block tile, 8x8 FFMA2 micro-tile per thread (256 threads).
// A row m: cols [0,KA) from A1 (ld lda1), cols [KA,K) from A2 (ld lda2).
// W is [N,K] row major. C is [M,N] row major. M must be multiple of 128.
__global__ __launch_bounds__(256, 1) void gemm_atb(
    const float* __restrict__ A1, int lda1, int KA,
    const float* __restrict__ A2, int lda2,
    const float* __restrict__ W, const float* __restrict__ bias,
    float* __restrict__ C, int N, int K, int act)
{
    __shared__ float As[128][20];
    __shared__ float Ws[128][20];
    int tid = threadIdx.x;
    int tx = tid & 15, ty = tid >> 4;
    int m0 = blockIdx.x * 128, n0 = blockIdx.y * 128;

    ull acc[8][8];
#pragma unroll
    for (int i = 0; i < 8; i++)
#pragma unroll
        for (int j = 0; j < 8; j++) acc[i][j] = 0ULL;

    float4 pa[2], pw[2];
    int ntiles = (K + 15) / 16;

    // ---- load one k-tile into registers ----
#define GEMM_LOAD(k0)                                                          \
    {                                                                          \
        _Pragma("unroll")                                                      \
        for (int q = 0; q < 2; q++) {                                          \
            int id = tid * 2 + q;                                              \
            int row = id >> 2, ch = id & 3;                                    \
            int k = (k0) + ch * 4;                                             \
            float4 v = make_float4(0.f, 0.f, 0.f, 0.f);                        \
            size_t m = (size_t)(m0 + row);                                     \
            if (k + 4 <= KA) v = *(const float4*)&A1[m * (size_t)lda1 + k];    \
            else if (k >= KA && k + 4 <= K)                                    \
                v = *(const float4*)&A2[m * (size_t)lda2 + (k - KA)];          \
            else {                                                             \
                float t0[4];                                                   \
                _Pragma("unroll")                                              \
                for (int e = 0; e < 4; e++) {                                  \
                    int ke = k + e;                                            \
                    t0[e] = (ke < K) ? ((ke < KA) ? A1[m * (size_t)lda1 + ke]  \
                                                  : A2[m * (size_t)lda2 + ke - KA]) \
                                     : 0.f;                                    \
                }                                                              \
                v = make_float4(t0[0], t0[1], t0[2], t0[3]);                   \
            }                                                                  \
            pa[q] = v;                                                         \
            int n = n0 + row;                                                  \
            float4 w = make_float4(0.f, 0.f, 0.f, 0.f);                        \
            if (n < N) {                                                       \
                if (k + 4 <= K) w = *(const float4*)&W[(size_t)n * K + k];     \
                else {                                                         \
                    float t1[4];                                               \
                    _Pragma("unroll")                                          \
                    for (int e = 0; e < 4; e++) {                              \
                        int ke = k + e;                                        \
                        t1[e] = (ke < K) ? W[(size_t)n * K + ke] : 0.f;        \
                    }                                                          \
                    w = make_float4(t1[0], t1[1], t1[2], t1[3]);               \
                }                                                              \
            }                                                                  \
            pw[q] = w;                                                         \
        }                                                                      \
    }

#define GEMM_STORE()                                                           \
    {                                                                          \
        _Pragma("unroll")                                                      \
        for (int q = 0; q < 2; q++) {                                          \
            int id = tid * 2 + q;                                              \
            int row = id >> 2, ch = id & 3;                                    \
            *(float4*)&As[row][ch * 4] = pa[q];                                \
            *(float4*)&Ws[row][ch * 4] = pw[q];                                \
        }                                                                      \
    }

    GEMM_LOAD(0);
    GEMM_STORE();

    for (int t = 0; t < ntiles; t++) {
        __syncthreads();
        if (t + 1 < ntiles) GEMM_LOAD((t + 1) * 16);
#pragma unroll
        for (int kk = 0; kk < 16; kk += 2) {
            ull a2[8], w2[8];
#pragma unroll
            for (int i = 0; i < 8; i++) a2[i] = *(const ull*)&As[ty + 16 * i][kk];
#pragma unroll
            for (int j = 0; j < 8; j++) w2[j] = *(const ull*)&Ws[tx + 16 * j][kk];
#pragma unroll
            for (int i = 0; i < 8; i++)
#pragma unroll
                for (int j = 0; j < 8; j++) ffma2(acc[i][j], a2[i], w2[j]);
        }
        __syncthreads();
        if (t + 1 < ntiles) GEMM_STORE();
    }

#pragma unroll
    for (int i = 0; i < 8; i++) {
        int m = m0 + ty + 16 * i;
#pragma unroll
        for (int j = 0; j < 8; j++) {
            int n = n0 + tx + 16 * j;
            if (n < N) {
                float v = f2sum(acc[i][j]) + bias[n];
                if (act) v = fmaxf(v, 0.f);
                C[(size_t)m * N + n] = v;
            }
        }
    }
#undef GEMM_LOAD
#undef GEMM_STORE
}

// ---------------- GRU step (both directions, gates fused) -------------------
// block: 128 batches x 16 h-cols (x3 gates). 128 threads, 8x(2x3) micro-tile.
__global__ __launch_bounds__(128, 1) void gru_step(
    const float* __restrict__ Whh_f, const float* __restrict__ bhh_f,
    const float* __restrict__ Whh_b, const float* __restrict__ bhh_b,
    int t)
{
    int dir = blockIdx.z;
    const float* Whh = dir ? Whh_b : Whh_f;
    const float* bhh = dir ? bhh_b : bhh_f;
    const float* gx = dir ? g_gx_b : g_gx_f;
    float* hout = dir ? g_hb : g_hf;
    int s = dir ? (Sn - 1 - t) : t;
    int p = t & 1;
    const float* hprev = g_hcur[p][dir];
    float* hnext = g_hcur[p ^ 1][dir];

    __shared__ float hs[128][20];
    __shared__ float ws[48][20];

    int tid = threadIdx.x;
    int tx = tid & 7, ty = tid >> 3;
    int b0 = blockIdx.x * 128, j0 = blockIdx.y * 16;

    ull acc[8][2][3];
#pragma unroll
    for (int i = 0; i < 8; i++)
#pragma unroll
        for (int jj = 0; jj < 2; jj++)
#pragma unroll
            for (int g = 0; g < 3; g++) acc[i][jj][g] = 0ULL;

    float4 ph[4], pw[2];
    const int ntiles = (Hn + 15) / 16;  // 13

#define GRU_LOAD(k0)                                                           \
    {                                                                          \
        size_t hb = (size_t)(b0 + tid) * Hn;                                   \
        _Pragma("unroll")                                                      \
        for (int q = 0; q < 4; q++) {                                          \
            int k = (k0) + q * 4;                                              \
            float4 v = make_float4(0.f, 0.f, 0.f, 0.f);                        \
            if (k + 4 <= Hn) v = *(const float4*)&hprev[hb + k];               \
            else {                                                             \
                float t0[4];                                                   \
                _Pragma("unroll")                                              \
                for (int e = 0; e < 4; e++)                                    \
                    t0[e] = (k + e < Hn) ? hprev[hb + k + e] : 0.f;            \
                v = make_float4(t0[0], t0[1], t0[2], t0[3]);                   \
            }                                                                  \
            ph[q] = v;                                                         \
        }                                                                      \
        _Pragma("unroll")                                                      \
        for (int q = 0; q < 2; q++) {                                          \
            int id = tid + 128 * q;                                            \
            float4 v = make_float4(0.f, 0.f, 0.f, 0.f);                        \
            if (id < 192) {                                                    \
                int row = id >> 2, ch = id & 3;                                \
                int k = (k0) + ch * 4;                                         \
                int g = row >> 4, jr = row & 15;                               \
                int j = j0 + jr;                                               \
                if (j < Hn) {                                                  \
                    size_t off = ((size_t)g * Hn + j) * Hn;                    \
                    if (k + 4 <= Hn) v = *(const float4*)&Whh[off + k];        \
                    else {                                                     \
                        float t1[4];                                           \
                        _Pragma("unroll")                                      \
                        for (int e = 0; e < 4; e++)                            \
                            t1[e] = (k + e < Hn) ? Whh[off + k + e] : 0.f;     \
                        v = make_float4(t1[0], t1[1], t1[2], t1[3]);           \
                    }                                                          \
                }                                                              \
            }                                                                  \
            pw[q] = v;                                                         \
        }                                                                      \
    }

#define GRU_STORE()                                                            \
    {                                                                          \
        _Pragma("unroll")                                                      \
        for (int q = 0; q < 4; q++) *(float4*)&hs[tid][q * 4] = ph[q];         \
        _Pragma("unroll")                                                      \
        for (int q = 0; q < 2; q++) {                                          \
            int id = tid + 128 * q;                                            \
            if (id < 192) {                                                    \
                int row = id >> 2, ch = id & 3;                                \
                *(float4*)&ws[row][ch * 4] = pw[q];                            \
            }                                                                  \
        }                                                                      \
    }

    GRU_LOAD(0);
    GRU_STORE();

    for (int tt = 0; tt < ntiles; tt++) {
        __syncthreads();
        if (tt + 1 < ntiles) GRU_LOAD((tt + 1) * 16);
#pragma unroll
        for (int kk = 0; kk < 16; kk += 2) {
            ull a2[8];
#pragma unroll
            for (int i = 0; i < 8; i++) a2[i] = *(const ull*)&hs[ty + 16 * i][kk];
#pragma unroll
            for (int g = 0; g < 3; g++) {
#pragma unroll
                for (int jj = 0; jj < 2; jj++) {
                    ull w2 = *(const ull*)&ws[g * 16 + tx + 8 * jj][kk];
#pragma unroll
                    for (int i = 0; i < 8; i++) ffma2(acc[i][jj][g], a2[i], w2);
                }
            }
        }
        __syncthreads();
        if (tt + 1 < ntiles) GRU_STORE();
    }

#pragma unroll
    for (int i = 0; i < 8; i++) {
#pragma unroll
        for (int jj = 0; jj < 2; jj++) {
            int b = b0 + ty + 16 * i;
            int j = j0 + tx + 8 * jj;
            if (j < Hn) {
                float ghr = f2sum(acc[i][jj][0]) + bhh[j];
                float ghz = f2sum(acc[i][jj][1]) + bhh[Hn + j];
                float ghn = f2sum(acc[i][jj][2]) + bhh[2 * Hn + j];
                size_t gxi = ((size_t)b * Sn + s) * G3 + j;
                float rg = sigf(gx[gxi] + ghr);
                float zg = sigf(gx[gxi + Hn] + ghz);
                float ng = tanhf(gx[gxi + 2 * Hn] + rg * ghn);
                float hp = hprev[(size_t)b * Hn + j];
                float hv = (1.f - zg) * ng + zg * hp;
                hnext[(size_t)b * Hn + j] = hv;
                hout[((size_t)b * Sn + s) * Hn + j] = hv;
            }
        }
    }
#undef GRU_LOAD
#undef GRU_STORE
}

// ---------------- avg over S ------------------------------------------------
__global__ void avg_kernel(const int* __restrict__ length) {
    int idx = blockIdx.x * blockDim.x + threadIdx.x;
    if (idx >= Bn * Hn) return;
    int b = idx / Hn, h = idx % Hn;
    float sm = 0.f;
#pragma unroll 10
    for (int t = 0; t < Sn; t++) sm += g_sent[((size_t)b * Sn + t) * Hn + h];
    g_avg[idx] = sm / (float)length[b];
}

// ---------------- doc = tanh(avg@W1^T+b1)@W2^T+b2 ---------------------------
__global__ __launch_bounds__(256) void doc_kernel(
    const float* __restrict__ W1, const float* __restrict__ b1,
    const float* __restrict__ W2, const float* __restrict__ b2)
{
    __shared__ float sv[Hn];
    __shared__ float st[Hn];
    int b = blockIdx.x, tid = threadIdx.x;
    if (tid < Hn) sv[tid] = g_avg[b * Hn + tid];
    __syncthreads();
    if (tid < Hn) {
        float a = b1[tid];
        for (int k = 0; k < Hn; k++) a += sv[k] * W1[(size_t)tid * Hn + k];
        st[tid] = tanhf(a);
    }
    __syncthreads();
    if (tid < Hn) {
        float a = b2[tid];
        for (int k = 0; k < Hn; k++) a += st[k] * W2[(size_t)tid * Hn + k];
        g_doc[b * Hn + tid] = a;
    }
}

// ---------------- base += content + salience --------------------------------
__global__ __launch_bounds__(256) void basedot_kernel(
    const float* __restrict__ wcont, const float* __restrict__ bcont)
{
    int row = blockIdx.x * 8 + (threadIdx.x >> 5);
    int lane = threadIdx.x & 31;
    int b = row / Sn;
    float a1 = 0.f, a2 = 0.f;
    for (int h = lane; h < Hn; h += 32) {
        float sv = g_sent[(size_t)row * Hn + h];
        a1 += sv * wcont[h];
        a2 += sv * g_doc[b * Hn + h];
    }
#pragma unroll
    for (int o = 16; o; o >>= 1) {
        a1 += __shfl_xor_sync(0xffffffffu, a1, o);
        a2 += __shfl_xor_sync(0xffffffffu, a2, o);
    }
    if (lane == 0) g_base[row] += a1 + bcont[0] + a2;
}

// ---------------- final novelty scan ---------------------------------------
__global__ __launch_bounds__(256) void scan_kernel(float* __restrict__ out) {
    __shared__ float red[8];
    int b = blockIdx.x, tid = threadIdx.x;
    int lane = tid & 31, w = tid >> 5;
    bool act = tid < Hn;
    float summ = 0.f;
    for (int t = 0; t < Sn; t++) {
        float part = 0.f;
        size_t off = ((size_t)b * Sn + t) * Hn + tid;
        if (act) part = g_novp[off] * tanhf(summ);
#pragma unroll
        for (int o = 16; o; o >>= 1) part += __shfl_xor_sync(0xffffffffu, part, o);
        if (lane == 0) red[w] = part;
        __syncthreads();
        float tot = red[0] + red[1] + red[2] + red[3] + red[4] + red[5] + red[6] + red[7];
        float logit = g_base[b * Sn + t] - tot;
        float sg = 1.f / (1.f + expf(-logit));
        if (act) summ += g_sent[off] * sg;
        if (tid == 0) out[b * Sn + t] = logit;
        __syncthreads();
    }
}

// ---------------- launch ----------------------------------------------------
extern "C" void kernel_launch(void* const* d_in, const int* in_sizes, int n_in,
                              void* d_out, int out_size) {
    const float* seq       = (const float*)d_in[0];
    const int*   apos      = (const int*)d_in[1];
    const int*   rpos      = (const int*)d_in[2];
    const int*   length    = (const int*)d_in[3];
    const float* apos_table= (const float*)d_in[4];
    const float* rpos_table= (const float*)d_in[5];
    const float* apos_w    = (const float*)d_in[6];
    const float* apos_b    = (const float*)d_in[7];
    const float* rpos_w    = (const float*)d_in[8];
    const float* rpos_b    = (const float*)d_in[9];
    const float* Wih_f     = (const float*)d_in[10];
    const float* Whh_f     = (const float*)d_in[11];
    const float* bih_f     = (const float*)d_in[12];
    const float* bhh_f     = (const float*)d_in[13];
    const float* Wih_b     = (const float*)d_in[14];
    const float* Whh_b     = (const float*)d_in[15];
    const float* bih_b     = (const float*)d_in[16];
    const float* bhh_b     = (const float*)d_in[17];
    const float* Wsent     = (const float*)d_in[18];
    const float* bsent     = (const float*)d_in[19];
    const float* wcont     = (const float*)d_in[20];
    const float* bcont     = (const float*)d_in[21];
    const float* Wdoc1     = (const float*)d_in[22];
    const float* bdoc1     = (const float*)d_in[23];
    const float* Wdoc2     = (const float*)d_in[24];
    const float* bdoc2     = (const float*)d_in[25];
    const float* Wnov      = (const float*)d_in[26];
    const float* bnov      = (const float*)d_in[27];
    const float* bias      = (const float*)d_in[28];

    float *p_gxf, *p_gxb, *p_hf, *p_hb, *p_sent, *p_novp, *p_hcur;
    cudaGetSymbolAddress((void**)&p_gxf,  g_gx_f);
    cudaGetSymbolAddress((void**)&p_gxb,  g_gx_b);
    cudaGetSymbolAddress((void**)&p_hf,   g_hf);
    cudaGetSymbolAddress((void**)&p_hb,   g_hb);
    cudaGetSymbolAddress((void**)&p_sent, g_sent);
    cudaGetSymbolAddress((void**)&p_novp, g_novp);
    cudaGetSymbolAddress((void**)&p_hcur, g_hcur);

    // zero initial h state (parity 0, both dirs)
    {
        int n = 2 * Bn * Hn;
        zero_kernel<<<(n + 255) / 256, 256>>>(p_hcur, n);
    }

    // position logits + bias
    pos_kernel<<<(Bn * Sn + 255) / 256, 256>>>(apos, rpos, apos_table, rpos_table,
                                               apos_w, apos_b, rpos_w, rpos_b, bias);

    // gx GEMMs: [51200,300] @ [600,300]^T
    gemm_atb<<<dim3(Bn * Sn / 128, (G3 + 127) / 128), 256>>>(
        seq, En, En, seq, En, Wih_f, bih_f, p_gxf, G3, En, 0);
    gemm_atb<<<dim3(Bn * Sn / 128, (G3 + 127) / 128), 256>>>(
        seq, En, En, seq, En, Wih_b, bih_b, p_gxb, G3, En, 0);

    // GRU recurrence
    for (int t = 0; t < Sn; t++) {
        gru_step<<<dim3(Bn / 128, (Hn + 15) / 16, 2), 128>>>(Whh_f, bhh_f, Whh_b, bhh_b, t);
    }

    // sent = relu([hf|hb] @ Wsent^T + bsent)
    gemm_atb<<<dim3(Bn * Sn / 128, (Hn + 127) / 128), 256>>>(
        p_hf, Hn, Hn, p_hb, Hn, Wsent, bsent, p_sent, Hn, 2 * Hn, 1);

    // avg over S, doc MLP
    avg_kernel<<<(Bn * Hn + 255) / 256, 256>>>(length);
    doc_kernel<<<Bn, 256>>>(Wdoc1, bdoc1, Wdoc2, bdoc2);

    // nov_pre = sent @ Wnov^T + bnov
    gemm_atb<<<dim3(Bn * Sn / 128, (Hn + 127) / 128), 256>>>(
        p_sent, Hn, Hn, p_sent, Hn, Wnov, bnov, p_novp, Hn, Hn, 0);

    // base += content + salience
    basedot_kernel<<<Bn * Sn / 8, 256>>>(wcont, bcont);

    // final scan -> logits
    scan_kernel<<<Bn, 256>>>((float*)d_out);
}